// round 9
// baseline (speedup 1.0000x reference)
#include <cuda_runtime.h>

// LocalVariation: out[b, k, y, x] = x[b,y,x] - xp[b, y+i, x+j]  (replicate pad, 5x5, skip center)
// Input : [16, 1, 512, 512] f32
// Output: [16, 24, 512, 512] f32
//
// Tile: 128 (x) by 8 (y) pixels per block, blockDim (32,8)=256 threads.
// Each thread computes 4 consecutive x pixels -> float4 streaming stores, 24 channels.
// launch_bounds(256,8) -> 2048 thr/SM ceiling, forces regs<=32 (rows re-read
// from smem per stencil row, so the live set fits without spilling).

#define KSZ   5
#define PAD   2
#define H     512
#define W     512
#define B     16
#define NCH   24
#define TILE_X 128
#define TILE_Y 8
#define SM_W  (TILE_X + 2 * PAD)   // 132 valid cols
#define SM_STRIDE 136              // 16B-aligned row stride
#define SM_H  (TILE_Y + 2 * PAD)   // 12 rows
#define SM_ELEMS (SM_H * SM_W)     // 1584

__global__ __launch_bounds__(256, 8)
void localvar_kernel(const float* __restrict__ in, float* __restrict__ out) {
    __shared__ float sm[SM_H * SM_STRIDE];

    const int b   = blockIdx.z;
    const int by0 = blockIdx.y * TILE_Y;
    const int bx0 = blockIdx.x * TILE_X;

    const int tid = threadIdx.y * 32 + threadIdx.x;
    const float* inb = in + b * (H * W);

    // ---- fill smem tile with replicate-clamped input ----
    // 1584 elements / 256 threads -> fixed 7 iterations, fully unrolled (MLP).
    #pragma unroll
    for (int it = 0; it < 7; it++) {
        int idx = tid + it * 256;
        if (idx < SM_ELEMS) {
            int r = idx / SM_W;
            int c = idx - r * SM_W;
            int gy = by0 + r - PAD;
            int gx = bx0 + c - PAD;
            gy = gy < 0 ? 0 : (gy > H - 1 ? H - 1 : gy);
            gx = gx < 0 ? 0 : (gx > W - 1 ? W - 1 : gx);
            sm[r * SM_STRIDE + c] = inb[gy * W + gx];
        }
    }
    __syncthreads();

    // ---- compute ----
    const int tx = threadIdx.x;       // 0..31
    const int ty = threadIdx.y;       // 0..7
    const int px = tx * 4;            // local x of first of 4 pixels

    // Center pixels: sm[ty+PAD][px+PAD .. px+PAD+3], 8B-aligned -> two LDS.64
    const float2 cA = *(const float2*)&sm[(ty + PAD) * SM_STRIDE + px + 2];
    const float2 cB = *(const float2*)&sm[(ty + PAD) * SM_STRIDE + px + 4];
    const float c0 = cA.x, c1 = cA.y, c2 = cB.x, c3 = cB.y;

    const int gy  = by0 + ty;
    const int gx0 = bx0 + px;
    float* outp = out + ((long long)b * NCH * H + gy) * W + gx0;

    int k = 0;
    #pragma unroll
    for (int i = 0; i < KSZ; i++) {
        // Load this row's 8 floats (16B-aligned pair of LDS.128)
        const float4* p = (const float4*)&sm[(ty + i) * SM_STRIDE + px];
        float4 a = p[0];
        float4 d = p[1];
        float rr[8] = {a.x, a.y, a.z, a.w, d.x, d.y, d.z, d.w};

        #pragma unroll
        for (int j = 0; j < KSZ; j++) {
            if (i == PAD && j == PAD) continue;
            float4 v;
            v.x = c0 - rr[j + 0];
            v.y = c1 - rr[j + 1];
            v.z = c2 - rr[j + 2];
            v.w = c3 - rr[j + 3];
            __stcs((float4*)(outp + (long long)k * (H * W)), v);
            k++;
        }
    }
}

extern "C" void kernel_launch(void* const* d_in, const int* in_sizes, int n_in,
                              void* d_out, int out_size) {
    const float* x = (const float*)d_in[0];
    float* out = (float*)d_out;
    dim3 block(32, 8, 1);
    dim3 grid(W / TILE_X, H / TILE_Y, B);
    localvar_kernel<<<grid, block>>>(x, out);
}

// round 10
// speedup vs baseline: 1.0325x; 1.0325x over previous
#include <cuda_runtime.h>

// LocalVariation: out[b, k, y, x] = x[b,y,x] - xp[b, y+i, x+j]  (replicate pad, 5x5, skip center)
// Input : [16, 1, 512, 512] f32
// Output: [16, 24, 512, 512] f32
//
// Tile: 512 (x, full row) by 4 (y), blockDim (128,4)=512 threads.
// Each thread computes 4 consecutive x pixels -> float4 streaming stores, 24 channels.
// Per (block, channel) the write region is 4 full 2KB rows = 8KB contiguous,
// maximizing DRAM row-buffer locality (vs 512B fragments at 2KB stride before).

#define KSZ   5
#define PAD   2
#define H     512
#define W     512
#define B     16
#define NCH   24
#define TILE_X 512
#define TILE_Y 4
#define SM_W  (TILE_X + 2 * PAD)   // 516 valid cols
#define SM_STRIDE 520              // 16B-aligned row stride (520*4 = 2080 B)
#define SM_H  (TILE_Y + 2 * PAD)   // 8 rows
#define SM_ELEMS (SM_H * SM_W)     // 4128

__global__ __launch_bounds__(512, 4)
void localvar_kernel(const float* __restrict__ in, float* __restrict__ out) {
    __shared__ float sm[SM_H * SM_STRIDE];   // 16640 B

    const int b   = blockIdx.y;
    const int by0 = blockIdx.x * TILE_Y;

    const int tid = threadIdx.y * 128 + threadIdx.x;
    const float* inb = in + b * (H * W);

    // ---- fill smem tile with replicate-clamped input ----
    // 4128 elements / 512 threads -> fixed 9 iterations, fully unrolled (MLP).
    #pragma unroll
    for (int it = 0; it < 9; it++) {
        int idx = tid + it * 512;
        if (idx < SM_ELEMS) {
            int r = idx / SM_W;
            int c = idx - r * SM_W;
            int gy = by0 + r - PAD;
            int gx = c - PAD;                 // tile spans full row: bx0 = 0
            gy = gy < 0 ? 0 : (gy > H - 1 ? H - 1 : gy);
            gx = gx < 0 ? 0 : (gx > W - 1 ? W - 1 : gx);
            sm[r * SM_STRIDE + c] = inb[gy * W + gx];
        }
    }
    __syncthreads();

    // ---- compute ----
    const int tx = threadIdx.x;       // 0..127
    const int ty = threadIdx.y;       // 0..3
    const int px = tx * 4;            // local x of first of 4 pixels (0..508)

    // Center pixels: sm[ty+PAD][px+PAD .. px+PAD+3], 8B-aligned -> two LDS.64
    const float2 cA = *(const float2*)&sm[(ty + PAD) * SM_STRIDE + px + 2];
    const float2 cB = *(const float2*)&sm[(ty + PAD) * SM_STRIDE + px + 4];
    const float c0 = cA.x, c1 = cA.y, c2 = cB.x, c3 = cB.y;

    const int gy = by0 + ty;
    float* outp = out + ((long long)b * NCH * H + gy) * W + px;

    int k = 0;
    #pragma unroll
    for (int i = 0; i < KSZ; i++) {
        // Load this row's 8 floats (16B-aligned pair of LDS.128)
        const float4* p = (const float4*)&sm[(ty + i) * SM_STRIDE + px];
        float4 a = p[0];
        float4 d = p[1];
        float rr[8] = {a.x, a.y, a.z, a.w, d.x, d.y, d.z, d.w};

        #pragma unroll
        for (int j = 0; j < KSZ; j++) {
            if (i == PAD && j == PAD) continue;
            float4 v;
            v.x = c0 - rr[j + 0];
            v.y = c1 - rr[j + 1];
            v.z = c2 - rr[j + 2];
            v.w = c3 - rr[j + 3];
            __stcs((float4*)(outp + (long long)k * (H * W)), v);
            k++;
        }
    }
}

extern "C" void kernel_launch(void* const* d_in, const int* in_sizes, int n_in,
                              void* d_out, int out_size) {
    const float* x = (const float*)d_in[0];
    float* out = (float*)d_out;
    dim3 block(128, 4, 1);
    dim3 grid(H / TILE_Y, B, 1);    // 128 x 16 = 2048 blocks
    localvar_kernel<<<grid, block>>>(x, out);
}